// round 5
// baseline (speedup 1.0000x reference)
#include <cuda_runtime.h>
#include <cuda_bf16.h>
#include <math_constants.h>

#define BB 4
#define NN 256
#define DD 128
#define HH 256          // 2*D
#define BN (BB*NN)      // 1024 rows
#define NTILES 16
#define NPAIRT 136      // 16*17/2

__device__ float g_Amat[BN * HH];   // A[row,h] = s_row @ W1a + b1
__device__ float g_Bmat[BN * HH];   // B[row,h] = s_row @ W1b
__device__ float g_scores[BB * NN * NN];

typedef unsigned long long ull;

__device__ __forceinline__ void upk2(ull v, float& lo, float& hi) {
    asm("mov.b64 {%0, %1}, %2;" : "=f"(lo), "=f"(hi) : "l"(v));
}
__device__ __forceinline__ ull fma2(ull a, ull b, ull c) {
    ull r;
    asm("fma.rn.f32x2 %0, %1, %2, %3;" : "=l"(r) : "l"(a), "l"(b), "l"(c));
    return r;
}
__device__ __forceinline__ ull mul2(ull a, ull b) {
    ull r;
    asm("mul.rn.f32x2 %0, %1, %2;" : "=l"(r) : "l"(a), "l"(b));
    return r;
}

// ---------------------------------------------------------------------------
// Kernel 1: precompute A,B. 4 rows/CTA (grid 256), register double-buffered
// W1 chunk prefetch so LDG latency overlaps compute.
// ---------------------------------------------------------------------------
#define PR 4
__global__ void __launch_bounds__(256)
precompute_AB_kernel(const float* __restrict__ s,
                     const float* __restrict__ W1,
                     const float* __restrict__ b1) {
    __shared__ float  sv[PR][DD];
    __shared__ float4 WA4[2][16 * 64];   // double buffer: 16 d x 256 h
    __shared__ float4 WB4[2][16 * 64];

    const int row0 = blockIdx.x * PR;
    const int tid = threadIdx.x;

    for (int idx = tid; idx < PR * DD; idx += 256)
        sv[idx >> 7][idx & 127] = s[row0 * DD + idx];

    const float bias = b1[tid];
    float a[PR], bb[PR];
#pragma unroll
    for (int r = 0; r < PR; r++) { a[r] = bias; bb[r] = 0.f; }

    const float4* W1_4 = (const float4*)W1;  // row stride 64 float4

    // prefetch chunk 0 into registers
    float4 pa[4], pb[4];
#pragma unroll
    for (int k = 0; k < 4; k++) {
        int idx = k * 256 + tid;
        int d = idx >> 6, c = idx & 63;
        pa[k] = __ldg(&W1_4[d * 64 + c]);
        pb[k] = __ldg(&W1_4[(DD + d) * 64 + c]);
    }

    for (int ch = 0; ch < 8; ch++) {
        const int buf = ch & 1;
        __syncthreads();   // prior compute on this buffer done
#pragma unroll
        for (int k = 0; k < 4; k++) {
            WA4[buf][k * 256 + tid] = pa[k];
            WB4[buf][k * 256 + tid] = pb[k];
        }
        if (ch < 7) {
            const int d0 = (ch + 1) * 16;
#pragma unroll
            for (int k = 0; k < 4; k++) {
                int idx = k * 256 + tid;
                int d = idx >> 6, c = idx & 63;
                pa[k] = __ldg(&W1_4[(d0 + d) * 64 + c]);
                pb[k] = __ldg(&W1_4[(DD + d0 + d) * 64 + c]);
            }
        }
        __syncthreads();   // buffer filled
        const float* WA = (const float*)WA4[buf];
        const float* WB = (const float*)WB4[buf];
        const int d0 = ch * 16;
#pragma unroll
        for (int dd = 0; dd < 16; dd++) {
            float wa = WA[dd * 256 + tid];
            float wb = WB[dd * 256 + tid];
#pragma unroll
            for (int r = 0; r < PR; r++) {
                float sval = sv[r][d0 + dd];
                a[r]  = fmaf(sval, wa, a[r]);
                bb[r] = fmaf(sval, wb, bb[r]);
            }
        }
    }
#pragma unroll
    for (int r = 0; r < PR; r++) {
        g_Amat[(row0 + r) * HH + tid] = a[r];
        g_Bmat[(row0 + r) * HH + tid] = bb[r];
    }
}

// ---------------------------------------------------------------------------
// Kernel 2: symmetric score tiles.
// CTA = (b, ib<=jb) over 16x16 row tiles. 4 h-chunks of 64 h (32 float2).
// Thread map: hg = tid&3 (8 f32x2 each), jg = (tid>>2)&3 (4 j), ii = tid>>4.
// Per-thread acc: 4j x 8 f32x2 = 64 regs.
// ---------------------------------------------------------------------------
#define SIP 129   // sId pitch (float2)
#define SJP 18    // sJdT pitch (float2)
#define EPP 33    // epilogue tile pitch (float2)

#define SM2_TOTAL (16*SIP + 128*SJP + 128*32 + 4*16*EPP + 32)

__global__ void __launch_bounds__(256, 2)
score_tiles_kernel(const float* __restrict__ s,
                   const float* __restrict__ W1,
                   const float* __restrict__ W2) {
    extern __shared__ float2 sm2[];
    float2* sId  = sm2;                  // 16 x 129 : dup(s_i[d]) [i][d]
    float2* sJdT = sId + 16 * SIP;       // 128 x 18 : dup(s_j[d]) [d][j]
    float2* Wc   = sJdT + 128 * SJP;     // 128 x 32 : W1c chunk [d][q]
    float2* AiS  = Wc + 128 * 32;        // 16 x 33
    float2* BjS  = AiS + 16 * EPP;
    float2* AjS  = BjS + 16 * EPP;
    float2* BiS  = AjS + 16 * EPP;
    float2* W2S  = BiS + 16 * EPP;       // 32

    const int tid = threadIdx.x;
    int blk = blockIdx.x;
    const int b = blk / NPAIRT;
    int tp = blk % NPAIRT;
    int ib = 0;
    while (tp >= (NTILES - ib)) { tp -= (NTILES - ib); ib++; }
    const int jb = ib + tp;
    const bool mirror = (ib != jb);

    const int i0 = ib * 16, j0 = jb * 16;
    const int brow = b * NN;

    for (int idx = tid; idx < 16 * DD; idx += 256) {
        int r = idx >> 7, d = idx & 127;
        float vi = s[(brow + i0 + r) * DD + d];
        float vj = s[(brow + j0 + r) * DD + d];
        sId[r * SIP + d]  = make_float2(vi, vi);
        sJdT[d * SJP + r] = make_float2(vj, vj);
    }

    const int hg  = tid & 3;
    const int jg  = (tid >> 2) & 3;
    const int ii  = tid >> 4;
    const int jl  = jg * 4;

    const float4* W1c4 = (const float4*)(W1 + 2 * DD * HH);  // row stride 64
    const float2* A2   = (const float2*)g_Amat;
    const float2* B2   = (const float2*)g_Bmat;
    const float2* W22  = (const float2*)W2;

    float sF[4] = {0.f, 0.f, 0.f, 0.f};
    float sR[4] = {0.f, 0.f, 0.f, 0.f};

    for (int ch = 0; ch < 4; ch++) {
        __syncthreads();
        // Stage W1c chunk (64 h = 16 float4 per d-row)
        {
            float4* Wc4 = (float4*)Wc;
#pragma unroll
            for (int k = 0; k < 8; k++) {
                int idx = k * 256 + tid;
                int d = idx >> 4, c = idx & 15;
                Wc4[idx] = __ldg(&W1c4[d * 64 + ch * 16 + c]);
            }
        }
        // Stage epilogue slices (16 rows x 32 float2)
#pragma unroll
        for (int k = 0; k < 2; k++) {
            int idx = k * 256 + tid;
            int r = idx >> 5, q = idx & 31;
            AiS[r * EPP + q] = __ldg(&A2[(brow + i0 + r) * (HH / 2) + ch * 32 + q]);
            BjS[r * EPP + q] = __ldg(&B2[(brow + j0 + r) * (HH / 2) + ch * 32 + q]);
            if (mirror) {
                AjS[r * EPP + q] = __ldg(&A2[(brow + j0 + r) * (HH / 2) + ch * 32 + q]);
                BiS[r * EPP + q] = __ldg(&B2[(brow + i0 + r) * (HH / 2) + ch * 32 + q]);
            }
        }
        if (tid < 32) W2S[tid] = __ldg(&W22[ch * 32 + tid]);
        __syncthreads();

        ull acc[4][8];
#pragma unroll
        for (int p = 0; p < 4; p++)
#pragma unroll
            for (int t = 0; t < 8; t++) acc[p][t] = 0ULL;

#pragma unroll 2
        for (int d = 0; d < DD; d++) {
            ull siv = *(const ull*)&sId[ii * SIP + d];
            ulonglong2 sja = *(const ulonglong2*)&sJdT[d * SJP + jl];
            ulonglong2 sjb = *(const ulonglong2*)&sJdT[d * SJP + jl + 2];
            ull P0 = mul2(siv, sja.x);
            ull P1 = mul2(siv, sja.y);
            ull P2 = mul2(siv, sjb.x);
            ull P3 = mul2(siv, sjb.y);
            const ulonglong2* wr = (const ulonglong2*)&Wc[d * 32 + hg * 8];
            {
                ulonglong2 w01 = wr[0];
                ulonglong2 w23 = wr[1];
                acc[0][0] = fma2(P0, w01.x, acc[0][0]);
                acc[1][0] = fma2(P1, w01.x, acc[1][0]);
                acc[2][0] = fma2(P2, w01.x, acc[2][0]);
                acc[3][0] = fma2(P3, w01.x, acc[3][0]);
                acc[0][1] = fma2(P0, w01.y, acc[0][1]);
                acc[1][1] = fma2(P1, w01.y, acc[1][1]);
                acc[2][1] = fma2(P2, w01.y, acc[2][1]);
                acc[3][1] = fma2(P3, w01.y, acc[3][1]);
                acc[0][2] = fma2(P0, w23.x, acc[0][2]);
                acc[1][2] = fma2(P1, w23.x, acc[1][2]);
                acc[2][2] = fma2(P2, w23.x, acc[2][2]);
                acc[3][2] = fma2(P3, w23.x, acc[3][2]);
                acc[0][3] = fma2(P0, w23.y, acc[0][3]);
                acc[1][3] = fma2(P1, w23.y, acc[1][3]);
                acc[2][3] = fma2(P2, w23.y, acc[2][3]);
                acc[3][3] = fma2(P3, w23.y, acc[3][3]);
            }
            {
                ulonglong2 w45 = wr[2];
                ulonglong2 w67 = wr[3];
                acc[0][4] = fma2(P0, w45.x, acc[0][4]);
                acc[1][4] = fma2(P1, w45.x, acc[1][4]);
                acc[2][4] = fma2(P2, w45.x, acc[2][4]);
                acc[3][4] = fma2(P3, w45.x, acc[3][4]);
                acc[0][5] = fma2(P0, w45.y, acc[0][5]);
                acc[1][5] = fma2(P1, w45.y, acc[1][5]);
                acc[2][5] = fma2(P2, w45.y, acc[2][5]);
                acc[3][5] = fma2(P3, w45.y, acc[3][5]);
                acc[0][6] = fma2(P0, w67.x, acc[0][6]);
                acc[1][6] = fma2(P1, w67.x, acc[1][6]);
                acc[2][6] = fma2(P2, w67.x, acc[2][6]);
                acc[3][6] = fma2(P3, w67.x, acc[3][6]);
                acc[0][7] = fma2(P0, w67.y, acc[0][7]);
                acc[1][7] = fma2(P1, w67.y, acc[1][7]);
                acc[2][7] = fma2(P2, w67.y, acc[2][7]);
                acc[3][7] = fma2(P3, w67.y, acc[3][7]);
            }
        }

        // Epilogue for this chunk (q = hg*8 + t, h-pair index within chunk)
#pragma unroll
        for (int t = 0; t < 8; t++) {
            int q = hg * 8 + t;
            float2 w2v = W2S[q];
            float2 ai  = AiS[ii * EPP + q];
#pragma unroll
            for (int p = 0; p < 4; p++) {
                float v0, v1;
                upk2(acc[p][t], v0, v1);
                float2 bj = BjS[(jl + p) * EPP + q];
                sF[p] = fmaf(fmaxf(v0 + ai.x + bj.x, 0.f), w2v.x, sF[p]);
                sF[p] = fmaf(fmaxf(v1 + ai.y + bj.y, 0.f), w2v.y, sF[p]);
                if (mirror) {
                    float2 bi = BiS[ii * EPP + q];
                    float2 aj = AjS[(jl + p) * EPP + q];
                    sR[p] = fmaf(fmaxf(v0 + aj.x + bi.x, 0.f), w2v.x, sR[p]);
                    sR[p] = fmaf(fmaxf(v1 + aj.y + bi.y, 0.f), w2v.y, sR[p]);
                }
            }
        }
    }

    // Reduce over hg (lane bits 0-1)
#pragma unroll
    for (int p = 0; p < 4; p++) {
        sF[p] += __shfl_xor_sync(0xffffffffu, sF[p], 1);
        sF[p] += __shfl_xor_sync(0xffffffffu, sF[p], 2);
        sR[p] += __shfl_xor_sync(0xffffffffu, sR[p], 1);
        sR[p] += __shfl_xor_sync(0xffffffffu, sR[p], 2);
    }
    if (hg == 0) {
        const int ig = i0 + ii;
#pragma unroll
        for (int p = 0; p < 4; p++) {
            g_scores[(brow + ig) * NN + j0 + jl + p] = sF[p];
            if (mirror)
                g_scores[(brow + j0 + jl + p) * NN + ig] = sR[p];
        }
    }
}

// ---------------------------------------------------------------------------
// Kernel 3: per-row top-K + outputs
// ---------------------------------------------------------------------------
__global__ void __launch_bounds__(256, 4)
topk_out_kernel(const float* __restrict__ s,
                const int* __restrict__ Kp,
                float* __restrict__ ctx_out,
                float* __restrict__ gate_out,
                float* __restrict__ w_out,
                int writeGW) {
    __shared__ float scoreArr[NN];
    __shared__ float flagArr[NN];
    __shared__ int selIdx[NN];

    const int tid = threadIdx.x;
    const int lane = tid & 31;
    const int warp = tid >> 5;
    const int row = blockIdx.x;
    const int b = row >> 8;

    int kv = 8;
    if (Kp) {
        int raw = *Kp;
        if (raw < 1 || raw > 100000) {
            float f = __int_as_float(raw);
            raw = (int)f;
        }
        kv = raw;
    }
    if (kv > NN) kv = NN;
    if (kv < 0) kv = 0;

    scoreArr[tid] = g_scores[row * NN + tid];
    flagArr[tid] = 0.f;
    __syncthreads();

    if (warp == 0) {
        float v[8];
#pragma unroll
        for (int m = 0; m < 8; m++) v[m] = scoreArr[lane + (m << 5)];
        for (int t = 0; t < kv; t++) {
            float bv = v[0];
            int bm = 0;
#pragma unroll
            for (int m = 1; m < 8; m++)
                if (v[m] > bv) { bv = v[m]; bm = m; }
            int bi = lane + (bm << 5);
#pragma unroll
            for (int off = 16; off > 0; off >>= 1) {
                float ov = __shfl_xor_sync(0xffffffffu, bv, off);
                int   oi = __shfl_xor_sync(0xffffffffu, bi, off);
                if (ov > bv || (ov == bv && oi < bi)) { bv = ov; bi = oi; }
            }
            if (lane == (bi & 31)) v[bi >> 5] = -CUDART_INF_F;
            if (lane == 0) { selIdx[t] = bi; flagArr[bi] = 1.f; }
            __syncwarp();
        }
    }
    __syncthreads();

    float invK = (kv > 0) ? (1.f / (float)kv) : 0.f;
    if (writeGW) {
        float g = flagArr[tid];
        gate_out[row * NN + tid] = g;
        w_out[row * NN + tid] = g * invK;
    }
    if (tid < DD) {
        float a = 0.f;
        for (int t = 0; t < kv; t++) a += s[((b << 8) + selIdx[t]) * DD + tid];
        ctx_out[row * DD + tid] = a * invK;
    }
}

// ---------------------------------------------------------------------------
extern "C" void kernel_launch(void* const* d_in, const int* in_sizes, int n_in,
                              void* d_out, int out_size) {
    const float* s  = (const float*)d_in[0];
    const float* W1 = (const float*)d_in[1];
    const float* b1 = (const float*)d_in[2];
    const float* W2 = (const float*)d_in[3];
    const int* Kp = (n_in > 5) ? (const int*)d_in[5] : nullptr;

    const int n_ctx  = BN * DD;
    const int n_gate = BN * NN;
    float* ctx  = (float*)d_out;
    float* gate = ctx + n_ctx;
    float* wout = gate + n_gate;
    int writeGW = (out_size >= n_ctx + 2 * n_gate) ? 1 : 0;

    const int smem_bytes = SM2_TOTAL * (int)sizeof(float2);
    cudaFuncSetAttribute(score_tiles_kernel,
                         cudaFuncAttributeMaxDynamicSharedMemorySize, smem_bytes);

    precompute_AB_kernel<<<BN / PR, 256>>>(s, W1, b1);
    score_tiles_kernel<<<BB * NPAIRT, 256, smem_bytes>>>(s, W1, W2);
    topk_out_kernel<<<BN, 256>>>(s, Kp, ctx, gate, wout, writeGW);
}

// round 7
// speedup vs baseline: 1.3630x; 1.3630x over previous
#include <cuda_runtime.h>
#include <cuda_bf16.h>
#include <math_constants.h>

#define BB 4
#define NN 256
#define DD 128
#define HH 256          // 2*D
#define BN (BB*NN)      // 1024 rows
#define NTILES 16
#define NPAIRT 136      // 16*17/2

__device__ float g_Amat[BN * HH];   // A[row,h] = s_row @ W1a + b1
__device__ float g_Bmat[BN * HH];   // B[row,h] = s_row @ W1b
__device__ float g_scores[BB * NN * NN];

typedef unsigned long long ull;

__device__ __forceinline__ void upk2(ull v, float& lo, float& hi) {
    asm("mov.b64 {%0, %1}, %2;" : "=f"(lo), "=f"(hi) : "l"(v));
}
__device__ __forceinline__ ull fma2(ull a, ull b, ull c) {
    ull r;
    asm("fma.rn.f32x2 %0, %1, %2, %3;" : "=l"(r) : "l"(a), "l"(b), "l"(c));
    return r;
}
__device__ __forceinline__ ull mul2(ull a, ull b) {
    ull r;
    asm("mul.rn.f32x2 %0, %1, %2;" : "=l"(r) : "l"(a), "l"(b));
    return r;
}

// ---------------------------------------------------------------------------
// Kernel 1: precompute A,B. 4 rows/CTA (grid 256), register double-buffered
// W1 chunk prefetch so LDG latency overlaps compute. (R4 version, 15.5us)
// ---------------------------------------------------------------------------
#define PR 4
__global__ void __launch_bounds__(256)
precompute_AB_kernel(const float* __restrict__ s,
                     const float* __restrict__ W1,
                     const float* __restrict__ b1) {
    __shared__ float  sv[PR][DD];
    __shared__ float4 WA4[2][16 * 64];
    __shared__ float4 WB4[2][16 * 64];

    const int row0 = blockIdx.x * PR;
    const int tid = threadIdx.x;

    for (int idx = tid; idx < PR * DD; idx += 256)
        sv[idx >> 7][idx & 127] = s[row0 * DD + idx];

    const float bias = b1[tid];
    float a[PR], bb[PR];
#pragma unroll
    for (int r = 0; r < PR; r++) { a[r] = bias; bb[r] = 0.f; }

    const float4* W1_4 = (const float4*)W1;  // row stride 64 float4

    float4 pa[4], pb[4];
#pragma unroll
    for (int k = 0; k < 4; k++) {
        int idx = k * 256 + tid;
        int d = idx >> 6, c = idx & 63;
        pa[k] = __ldg(&W1_4[d * 64 + c]);
        pb[k] = __ldg(&W1_4[(DD + d) * 64 + c]);
    }

    for (int ch = 0; ch < 8; ch++) {
        const int buf = ch & 1;
        __syncthreads();
#pragma unroll
        for (int k = 0; k < 4; k++) {
            WA4[buf][k * 256 + tid] = pa[k];
            WB4[buf][k * 256 + tid] = pb[k];
        }
        if (ch < 7) {
            const int d0 = (ch + 1) * 16;
#pragma unroll
            for (int k = 0; k < 4; k++) {
                int idx = k * 256 + tid;
                int d = idx >> 6, c = idx & 63;
                pa[k] = __ldg(&W1_4[(d0 + d) * 64 + c]);
                pb[k] = __ldg(&W1_4[(DD + d0 + d) * 64 + c]);
            }
        }
        __syncthreads();
        const float* WA = (const float*)WA4[buf];
        const float* WB = (const float*)WB4[buf];
        const int d0 = ch * 16;
#pragma unroll
        for (int dd = 0; dd < 16; dd++) {
            float wa = WA[dd * 256 + tid];
            float wb = WB[dd * 256 + tid];
#pragma unroll
            for (int r = 0; r < PR; r++) {
                float sval = sv[r][d0 + dd];
                a[r]  = fmaf(sval, wa, a[r]);
                bb[r] = fmaf(sval, wb, bb[r]);
            }
        }
    }
#pragma unroll
    for (int r = 0; r < PR; r++) {
        g_Amat[(row0 + r) * HH + tid] = a[r];
        g_Bmat[(row0 + r) * HH + tid] = bb[r];
    }
}

// ---------------------------------------------------------------------------
// Kernel 2: symmetric score tiles (R3 shape: 2j x 8 f32x2 per thread,
// acc = 32 regs), occupancy 3 for latency hiding + better wave tail.
// CTA = (b, ib<=jb) over 16x16 row tiles. 8 h-chunks of 32 h (16 float2).
// Thread map: hg = tid&1, jg = (tid>>1)&7 (j pair = 2*jg), ii = tid>>4.
// ---------------------------------------------------------------------------
#define SIP 129   // sId pitch (float2)
#define SJP 18    // sJdT pitch (float2)
#define EPP 17    // epilogue tile pitch (float2)

#define SM2_TOTAL (16*SIP + 128*SJP + 128*16 + 4*16*EPP + 16)

__global__ void __launch_bounds__(256, 3)
score_tiles_kernel(const float* __restrict__ s,
                   const float* __restrict__ W1,
                   const float* __restrict__ W2) {
    extern __shared__ float2 sm2[];
    float2* sId  = sm2;                  // 16 x 129 : dup(s_i[d]) [i][d]
    float2* sJdT = sId + 16 * SIP;       // 128 x 18 : dup(s_j[d]) [d][j]
    float2* Wc   = sJdT + 128 * SJP;     // 128 x 16 : W1c chunk [d][q]
    float2* AiS  = Wc + 128 * 16;        // 16 x 17
    float2* BjS  = AiS + 16 * EPP;
    float2* AjS  = BjS + 16 * EPP;
    float2* BiS  = AjS + 16 * EPP;
    float2* W2S  = BiS + 16 * EPP;       // 16

    const int tid = threadIdx.x;
    int blk = blockIdx.x;
    const int b = blk / NPAIRT;
    int tp = blk % NPAIRT;
    int ib = 0;
    while (tp >= (NTILES - ib)) { tp -= (NTILES - ib); ib++; }
    const int jb = ib + tp;
    const bool mirror = (ib != jb);

    const int i0 = ib * 16, j0 = jb * 16;
    const int brow = b * NN;

    for (int idx = tid; idx < 16 * DD; idx += 256) {
        int r = idx >> 7, d = idx & 127;
        float vi = s[(brow + i0 + r) * DD + d];
        float vj = s[(brow + j0 + r) * DD + d];
        sId[r * SIP + d]  = make_float2(vi, vi);
        sJdT[d * SJP + r] = make_float2(vj, vj);
    }

    const int hg  = tid & 1;
    const int jg  = (tid >> 1) & 7;
    const int ii  = tid >> 4;
    const int jl  = jg * 2;

    const float2* W1c2 = (const float2*)(W1 + 2 * DD * HH);
    const float2* A2   = (const float2*)g_Amat;
    const float2* B2   = (const float2*)g_Bmat;
    const float2* W22  = (const float2*)W2;

    float sF0 = 0.f, sF1 = 0.f, sR0 = 0.f, sR1 = 0.f;

    for (int ch = 0; ch < 8; ch++) {
        __syncthreads();
#pragma unroll
        for (int k = 0; k < 8; k++) {
            int idx = k * 256 + tid;
            int d = idx >> 4, q = idx & 15;
            Wc[d * 16 + q] = __ldg(&W1c2[d * (HH / 2) + ch * 16 + q]);
        }
        {
            int r = tid >> 4, q = tid & 15;
            AiS[r * EPP + q] = __ldg(&A2[(brow + i0 + r) * (HH / 2) + ch * 16 + q]);
            BjS[r * EPP + q] = __ldg(&B2[(brow + j0 + r) * (HH / 2) + ch * 16 + q]);
            if (mirror) {
                AjS[r * EPP + q] = __ldg(&A2[(brow + j0 + r) * (HH / 2) + ch * 16 + q]);
                BiS[r * EPP + q] = __ldg(&B2[(brow + i0 + r) * (HH / 2) + ch * 16 + q]);
            }
            if (tid < 16) W2S[tid] = __ldg(&W22[ch * 16 + tid]);
        }
        __syncthreads();

        ull acc0[8], acc1[8];
#pragma unroll
        for (int t = 0; t < 8; t++) { acc0[t] = 0ULL; acc1[t] = 0ULL; }

#pragma unroll 4
        for (int d = 0; d < DD; d++) {
            ull siv = *(const ull*)&sId[ii * SIP + d];
            ulonglong2 sjp = *(const ulonglong2*)&sJdT[d * SJP + jl];
            ull P0 = mul2(siv, sjp.x);
            ull P1 = mul2(siv, sjp.y);
            const ulonglong2* wrow = (const ulonglong2*)&Wc[d * 16 + hg * 8];
            // interleave loads with use to keep w liveness short
            {
                ulonglong2 w = wrow[0];
                acc0[0] = fma2(P0, w.x, acc0[0]); acc1[0] = fma2(P1, w.x, acc1[0]);
                acc0[1] = fma2(P0, w.y, acc0[1]); acc1[1] = fma2(P1, w.y, acc1[1]);
            }
            {
                ulonglong2 w = wrow[1];
                acc0[2] = fma2(P0, w.x, acc0[2]); acc1[2] = fma2(P1, w.x, acc1[2]);
                acc0[3] = fma2(P0, w.y, acc0[3]); acc1[3] = fma2(P1, w.y, acc1[3]);
            }
            {
                ulonglong2 w = wrow[2];
                acc0[4] = fma2(P0, w.x, acc0[4]); acc1[4] = fma2(P1, w.x, acc1[4]);
                acc0[5] = fma2(P0, w.y, acc0[5]); acc1[5] = fma2(P1, w.y, acc1[5]);
            }
            {
                ulonglong2 w = wrow[3];
                acc0[6] = fma2(P0, w.x, acc0[6]); acc1[6] = fma2(P1, w.x, acc1[6]);
                acc0[7] = fma2(P0, w.y, acc0[7]); acc1[7] = fma2(P1, w.y, acc1[7]);
            }
        }

        // Epilogue for this chunk
#pragma unroll
        for (int t = 0; t < 8; t++) {
            int q = hg * 8 + t;
            float2 w2v = W2S[q];
            float2 ai  = AiS[ii * EPP + q];
            float v0, v1, u0, u1;
            upk2(acc0[t], v0, v1);
            upk2(acc1[t], u0, u1);
            float2 bj0 = BjS[jl * EPP + q];
            float2 bj1 = BjS[(jl + 1) * EPP + q];
            sF0 = fmaf(fmaxf(v0 + ai.x + bj0.x, 0.f), w2v.x, sF0);
            sF0 = fmaf(fmaxf(v1 + ai.y + bj0.y, 0.f), w2v.y, sF0);
            sF1 = fmaf(fmaxf(u0 + ai.x + bj1.x, 0.f), w2v.x, sF1);
            sF1 = fmaf(fmaxf(u1 + ai.y + bj1.y, 0.f), w2v.y, sF1);
            if (mirror) {
                float2 bi  = BiS[ii * EPP + q];
                float2 aj0 = AjS[jl * EPP + q];
                float2 aj1 = AjS[(jl + 1) * EPP + q];
                sR0 = fmaf(fmaxf(v0 + aj0.x + bi.x, 0.f), w2v.x, sR0);
                sR0 = fmaf(fmaxf(v1 + aj0.y + bi.y, 0.f), w2v.y, sR0);
                sR1 = fmaf(fmaxf(u0 + aj1.x + bi.x, 0.f), w2v.x, sR1);
                sR1 = fmaf(fmaxf(u1 + aj1.y + bi.y, 0.f), w2v.y, sR1);
            }
        }
    }

    // Reduce over hg (lane bit 0)
    sF0 += __shfl_xor_sync(0xffffffffu, sF0, 1);
    sF1 += __shfl_xor_sync(0xffffffffu, sF1, 1);
    sR0 += __shfl_xor_sync(0xffffffffu, sR0, 1);
    sR1 += __shfl_xor_sync(0xffffffffu, sR1, 1);

    if (hg == 0) {
        const int ig = i0 + ii;
        g_scores[(brow + ig) * NN + j0 + jl]     = sF0;
        g_scores[(brow + ig) * NN + j0 + jl + 1] = sF1;
        if (mirror) {
            g_scores[(brow + j0 + jl) * NN + ig]     = sR0;
            g_scores[(brow + j0 + jl + 1) * NN + ig] = sR1;
        }
    }
}

// ---------------------------------------------------------------------------
// Kernel 3: per-row top-K + outputs
// ---------------------------------------------------------------------------
__global__ void __launch_bounds__(256, 4)
topk_out_kernel(const float* __restrict__ s,
                const int* __restrict__ Kp,
                float* __restrict__ ctx_out,
                float* __restrict__ gate_out,
                float* __restrict__ w_out,
                int writeGW) {
    __shared__ float scoreArr[NN];
    __shared__ float flagArr[NN];
    __shared__ int selIdx[NN];

    const int tid = threadIdx.x;
    const int lane = tid & 31;
    const int warp = tid >> 5;
    const int row = blockIdx.x;
    const int b = row >> 8;

    int kv = 8;
    if (Kp) {
        int raw = *Kp;
        if (raw < 1 || raw > 100000) {
            float f = __int_as_float(raw);
            raw = (int)f;
        }
        kv = raw;
    }
    if (kv > NN) kv = NN;
    if (kv < 0) kv = 0;

    scoreArr[tid] = g_scores[row * NN + tid];
    flagArr[tid] = 0.f;
    __syncthreads();

    if (warp == 0) {
        float v[8];
#pragma unroll
        for (int m = 0; m < 8; m++) v[m] = scoreArr[lane + (m << 5)];
        for (int t = 0; t < kv; t++) {
            float bv = v[0];
            int bm = 0;
#pragma unroll
            for (int m = 1; m < 8; m++)
                if (v[m] > bv) { bv = v[m]; bm = m; }
            int bi = lane + (bm << 5);
#pragma unroll
            for (int off = 16; off > 0; off >>= 1) {
                float ov = __shfl_xor_sync(0xffffffffu, bv, off);
                int   oi = __shfl_xor_sync(0xffffffffu, bi, off);
                if (ov > bv || (ov == bv && oi < bi)) { bv = ov; bi = oi; }
            }
            if (lane == (bi & 31)) v[bi >> 5] = -CUDART_INF_F;
            if (lane == 0) { selIdx[t] = bi; flagArr[bi] = 1.f; }
            __syncwarp();
        }
    }
    __syncthreads();

    float invK = (kv > 0) ? (1.f / (float)kv) : 0.f;
    if (writeGW) {
        float g = flagArr[tid];
        gate_out[row * NN + tid] = g;
        w_out[row * NN + tid] = g * invK;
    }
    if (tid < DD) {
        float a = 0.f;
        for (int t = 0; t < kv; t++) a += s[((b << 8) + selIdx[t]) * DD + tid];
        ctx_out[row * DD + tid] = a * invK;
    }
}

// ---------------------------------------------------------------------------
extern "C" void kernel_launch(void* const* d_in, const int* in_sizes, int n_in,
                              void* d_out, int out_size) {
    const float* s  = (const float*)d_in[0];
    const float* W1 = (const float*)d_in[1];
    const float* b1 = (const float*)d_in[2];
    const float* W2 = (const float*)d_in[3];
    const int* Kp = (n_in > 5) ? (const int*)d_in[5] : nullptr;

    const int n_ctx  = BN * DD;
    const int n_gate = BN * NN;
    float* ctx  = (float*)d_out;
    float* gate = ctx + n_ctx;
    float* wout = gate + n_gate;
    int writeGW = (out_size >= n_ctx + 2 * n_gate) ? 1 : 0;

    const int smem_bytes = SM2_TOTAL * (int)sizeof(float2);
    cudaFuncSetAttribute(score_tiles_kernel,
                         cudaFuncAttributeMaxDynamicSharedMemorySize, smem_bytes);

    precompute_AB_kernel<<<BN / PR, 256>>>(s, W1, b1);
    score_tiles_kernel<<<BB * NPAIRT, 256, smem_bytes>>>(s, W1, W2);
    topk_out_kernel<<<BN, 256>>>(s, Kp, ctx, gate, wout, writeGW);
}